// round 11
// baseline (speedup 1.0000x reference)
#include <cuda_runtime.h>

// 3x3 VALID conv, 8192x8192 fp32 in -> 8190x8190 fp32 out, + scalar bias.
// R8 (90.6us): DRAM 76.4%, L1 39%, occ 65.9% (regs=40 -> 48 warps/SM).
// R10: accumulator rotation (3 acc quads instead of 3 row buffers) cuts ~12
// live regs; __launch_bounds__(128,14) -> 56 warps/SM for more MLP. Parity-
// shifted 16B-aligned STG.128 kept. All edge work (right cols on even rows,
// cols 0-1 on odd rows) folded into the single c==8188 thread.

#define IW 8192
#define OW 8190
#define OH 8190
#define RPT 16   // output rows per thread (even; row parity == iter parity)
#define TPB 128  // threads/block; 4 cols/thread -> 512 cols/block

__device__ __forceinline__ void tap(float acc[4], const float* d, int s,
                                    float W0, float W1, float W2) {
    #pragma unroll
    for (int j = 0; j < 4; j++) {
        acc[j] = fmaf(W0, d[s + j],     acc[j]);
        acc[j] = fmaf(W1, d[s + j + 1], acc[j]);
        acc[j] = fmaf(W2, d[s + j + 2], acc[j]);
    }
}

__global__ __launch_bounds__(TPB, 14) void Conv2D_35210141892837_kernel(
    const float* __restrict__ x,
    const float* __restrict__ wgt,
    const float* __restrict__ bias,
    float* __restrict__ out)
{
    const int c  = (blockIdx.x * TPB + threadIdx.x) * 4;   // 0..8188
    const int r0 = blockIdx.y * RPT;                       // even

    const float w00 = wgt[0], w01 = wgt[1], w02 = wgt[2];
    const float w10 = wgt[3], w11 = wgt[4], w12 = wgt[5];
    const float w20 = wgt[6], w21 = wgt[7], w22 = wgt[8];
    const float bv  = bias[0];

    // ---- single edge thread per y-block (c == 8188): handles
    //      even rows: cols 8188,8189 ; odd rows: cols 0,1 ----
    if (c == 8188) {
        for (int i = 0; i < RPT; i++) {
            const int r = r0 + i;
            if (r >= OH) break;
            const size_t base = (size_t)r * IW + ((r & 1) ? 0 : 8188);
            float4 t = *(const float4*)(x + base);
            float4 m = *(const float4*)(x + base + IW);
            float4 l = *(const float4*)(x + base + 2 * IW);
            float o0 = bv, o1 = bv;
            o0 = fmaf(w00, t.x, o0); o0 = fmaf(w01, t.y, o0); o0 = fmaf(w02, t.z, o0);
            o0 = fmaf(w10, m.x, o0); o0 = fmaf(w11, m.y, o0); o0 = fmaf(w12, m.z, o0);
            o0 = fmaf(w20, l.x, o0); o0 = fmaf(w21, l.y, o0); o0 = fmaf(w22, l.z, o0);
            o1 = fmaf(w00, t.y, o1); o1 = fmaf(w01, t.z, o1); o1 = fmaf(w02, t.w, o1);
            o1 = fmaf(w10, m.y, o1); o1 = fmaf(w11, m.z, o1); o1 = fmaf(w12, m.w, o1);
            o1 = fmaf(w20, l.y, o1); o1 = fmaf(w21, l.z, o1); o1 = fmaf(w22, l.w, o1);
            float* po = out + (size_t)r * OW + ((r & 1) ? 0 : 8188);
            *(float2*)(po) = make_float2(o0, o1);   // 8B-aligned both parities
        }
        return;
    }

    // ---- main path: c in [0, 8184]; loads cols c..c+7 (<= 8191, in-bounds).
    //      Even output rows use window s=0, odd rows s=2 (16B-aligned stores).
    float a[3][4];   // rotating accumulator quads
    float cur[8];    // current input row (transient)

    auto load8 = [&](int rr) {
        const float* p = x + (size_t)rr * IW + c;
        float4 u = *(const float4*)(p);
        float4 v = *(const float4*)(p + 4);
        cur[0]=u.x; cur[1]=u.y; cur[2]=u.z; cur[3]=u.w;
        cur[4]=v.x; cur[5]=v.y; cur[6]=v.z; cur[7]=v.w;
    };

    // Prologue: input rows r0 (starts out-row r0, s=0) and r0+1 (mid r0,
    // starts out-row r0+1, s=2). r0 <= 8176 so all loads in-bounds.
    load8(r0);
    a[0][0]=bv; a[0][1]=bv; a[0][2]=bv; a[0][3]=bv;
    tap(a[0], cur, 0, w00, w01, w02);
    load8(r0 + 1);
    tap(a[0], cur, 0, w10, w11, w12);
    a[1][0]=bv; a[1][1]=bv; a[1][2]=bv; a[1][3]=bv;
    tap(a[1], cur, 2, w00, w01, w02);

    const bool row_full = (r0 + RPT <= OH);

    if (row_full) {
        #pragma unroll
        for (int i = 2; i < RPT + 2; i++) {
            load8(r0 + i);                          // input row <= r0+17 <= 8177
            const int sb = (i & 1) ? 2 : 0;         // shift: bot row & start row
            const int sm = (i & 1) ? 0 : 2;         // shift: mid row
            float* ab = a[(i - 2) % 3];
            float* am = a[(i - 1) % 3];
            float* as = a[i % 3];
            tap(ab, cur, sb, w20, w21, w22);        // complete out-row r0+i-2
            *(float4*)(out + (size_t)(r0 + i - 2) * OW + c + sb) =
                make_float4(ab[0], ab[1], ab[2], ab[3]);
            tap(am, cur, sm, w10, w11, w12);
            if (i < RPT) {                          // start out-row r0+i
                as[0]=bv; as[1]=bv; as[2]=bv; as[3]=bv;
                tap(as, cur, sb, w00, w01, w02);
            }
        }
    } else {
        // Last y-block (r0 = 8176, 14 valid rows).
        #pragma unroll
        for (int i = 2; i < RPT + 2; i++) {
            const int rout = r0 + i - 2;
            if (rout >= OH) break;                  // input row rout+2 <= 8191
            load8(rout + 2);
            const int sb = (i & 1) ? 2 : 0;
            const int sm = (i & 1) ? 0 : 2;
            float* ab = a[(i - 2) % 3];
            float* am = a[(i - 1) % 3];
            float* as = a[i % 3];
            tap(ab, cur, sb, w20, w21, w22);
            *(float4*)(out + (size_t)rout * OW + c + sb) =
                make_float4(ab[0], ab[1], ab[2], ab[3]);
            tap(am, cur, sm, w10, w11, w12);
            if (i < RPT) {
                as[0]=bv; as[1]=bv; as[2]=bv; as[3]=bv;
                tap(as, cur, sb, w00, w01, w02);
            }
        }
    }
}

extern "C" void kernel_launch(void* const* d_in, const int* in_sizes, int n_in,
                              void* d_out, int out_size) {
    const float* x    = (const float*)d_in[0];
    const float* wgt  = (const float*)d_in[1];
    const float* bias = (const float*)d_in[2];
    float* out = (float*)d_out;

    dim3 block(TPB, 1, 1);
    dim3 grid((OW + TPB * 4 - 1) / (TPB * 4),   // 16
              (OH + RPT - 1) / RPT,             // 512
              1);
    Conv2D_35210141892837_kernel<<<grid, block>>>(x, wgt, bias, out);
}

// round 12
// speedup vs baseline: 1.0641x; 1.0641x over previous
#include <cuda_runtime.h>

// 3x3 VALID conv, 8192x8192 fp32 in -> 8190x8190 fp32 out, + scalar bias.
// R8 (90.6us): parity-shifted STG.128, DRAM 76.4%, occ 66%. R10 (acc rotation,
// occ 88%) REGRESSED -> binder is per-warp load/use slack, not warp count.
// R11 = R8 + prefetch distance 1 (4 rotating row buffers): next row's 2x
// LDG.128 issue before current row's 36 FMAs, giving each load a full
// iteration of compute + other-warp overlap to hide DRAM latency.

#define IW 8192
#define OW 8190
#define OH 8190
#define RPT 16   // output rows per thread; even -> row parity == iter parity
#define TPB 128  // threads/block; 4 cols/thread -> 512 cols/block

__global__ __launch_bounds__(TPB, 10) void Conv2D_35210141892837_kernel(
    const float* __restrict__ x,
    const float* __restrict__ wgt,
    const float* __restrict__ bias,
    float* __restrict__ out)
{
    const int c  = (blockIdx.x * TPB + threadIdx.x) * 4;   // 0..8188
    const int r0 = blockIdx.y * RPT;                       // even
    if (c >= OW) return;

    const float w00 = wgt[0], w01 = wgt[1], w02 = wgt[2];
    const float w10 = wgt[3], w11 = wgt[4], w12 = wgt[5];
    const float w20 = wgt[6], w21 = wgt[7], w22 = wgt[8];
    const float bv  = bias[0];

    // ---- single edge thread per y-block (c == 8188):
    //      even rows: cols 8188,8189 ; odd rows: cols 0,1 ----
    if (c == 8188) {
        for (int i = 0; i < RPT; i++) {
            const int r = r0 + i;
            if (r >= OH) break;
            const size_t base = (size_t)r * IW + ((r & 1) ? 0 : 8188);
            float4 t = *(const float4*)(x + base);
            float4 m = *(const float4*)(x + base + IW);
            float4 l = *(const float4*)(x + base + 2 * IW);
            float o0 = bv, o1 = bv;
            o0 = fmaf(w00, t.x, o0); o0 = fmaf(w01, t.y, o0); o0 = fmaf(w02, t.z, o0);
            o0 = fmaf(w10, m.x, o0); o0 = fmaf(w11, m.y, o0); o0 = fmaf(w12, m.z, o0);
            o0 = fmaf(w20, l.x, o0); o0 = fmaf(w21, l.y, o0); o0 = fmaf(w22, l.z, o0);
            o1 = fmaf(w00, t.y, o1); o1 = fmaf(w01, t.z, o1); o1 = fmaf(w02, t.w, o1);
            o1 = fmaf(w10, m.y, o1); o1 = fmaf(w11, m.z, o1); o1 = fmaf(w12, m.w, o1);
            o1 = fmaf(w20, l.y, o1); o1 = fmaf(w21, l.z, o1); o1 = fmaf(w22, l.w, o1);
            float* po = out + (size_t)r * OW + ((r & 1) ? 0 : 8188);
            *(float2*)(po) = make_float2(o0, o1);
        }
        return;
    }

    // ---- main path: c in [0, 8184]; loads cols c..c+7 (in-bounds).
    //      Even out-rows: window shift s=0; odd: s=2 -> 16B-aligned STG.128.
    float buf[4][8];   // rotating row buffers, prefetch distance 1

    auto load8 = [&](int rr, float* d) {
        const float* p = x + (size_t)rr * IW + c;
        float4 a = *(const float4*)(p);
        float4 b = *(const float4*)(p + 4);
        d[0]=a.x; d[1]=a.y; d[2]=a.z; d[3]=a.w;
        d[4]=b.x; d[5]=b.y; d[6]=b.z; d[7]=b.w;
    };

    // Preload input rows r0..r0+2 (r0 <= 8176 -> r0+2 <= 8178, in-bounds).
    load8(r0,     buf[0]);
    load8(r0 + 1, buf[1]);
    load8(r0 + 2, buf[2]);

    const bool row_full = (r0 + RPT <= OH);

    #pragma unroll
    for (int i = 0; i < RPT; i++) {
        const int r = r0 + i;
        if (!row_full && r >= OH) break;

        // Prefetch row r+3 (first used next iteration). Full blocks:
        // max r0+17 <= 8177. Tail block: guard r+3 <= 8191.
        if (i < RPT - 1 && (row_full || r + 3 < IW))
            load8(r + 3, buf[(i + 3) & 3]);

        const float* t = buf[ i      & 3];
        const float* m = buf[(i + 1) & 3];
        const float* l = buf[(i + 2) & 3];

        const int s = (i & 1) ? 2 : 0;                 // compile-time per iter

        float o0 = bv, o1 = bv, o2 = bv, o3 = bv;
        o0 = fmaf(w00, t[s+0], o0); o0 = fmaf(w01, t[s+1], o0); o0 = fmaf(w02, t[s+2], o0);
        o0 = fmaf(w10, m[s+0], o0); o0 = fmaf(w11, m[s+1], o0); o0 = fmaf(w12, m[s+2], o0);
        o0 = fmaf(w20, l[s+0], o0); o0 = fmaf(w21, l[s+1], o0); o0 = fmaf(w22, l[s+2], o0);
        o1 = fmaf(w00, t[s+1], o1); o1 = fmaf(w01, t[s+2], o1); o1 = fmaf(w02, t[s+3], o1);
        o1 = fmaf(w10, m[s+1], o1); o1 = fmaf(w11, m[s+2], o1); o1 = fmaf(w12, m[s+3], o1);
        o1 = fmaf(w20, l[s+1], o1); o1 = fmaf(w21, l[s+2], o1); o1 = fmaf(w22, l[s+3], o1);
        o2 = fmaf(w00, t[s+2], o2); o2 = fmaf(w01, t[s+3], o2); o2 = fmaf(w02, t[s+4], o2);
        o2 = fmaf(w10, m[s+2], o2); o2 = fmaf(w11, m[s+3], o2); o2 = fmaf(w12, m[s+4], o2);
        o2 = fmaf(w20, l[s+2], o2); o2 = fmaf(w21, l[s+3], o2); o2 = fmaf(w22, l[s+4], o2);
        o3 = fmaf(w00, t[s+3], o3); o3 = fmaf(w01, t[s+4], o3); o3 = fmaf(w02, t[s+5], o3);
        o3 = fmaf(w10, m[s+3], o3); o3 = fmaf(w11, m[s+4], o3); o3 = fmaf(w12, m[s+5], o3);
        o3 = fmaf(w20, l[s+3], o3); o3 = fmaf(w21, l[s+4], o3); o3 = fmaf(w22, l[s+5], o3);

        // (r*8190 + c + s) % 4 == 0 for both parities -> 16B-aligned STG.128.
        *(float4*)(out + (size_t)r * OW + c + s) = make_float4(o0, o1, o2, o3);

        if (s == 2 && c == 0) {
            // Odd rows: cols 0,1 not covered by shifted windows.
            float e0 = bv, e1 = bv;
            e0 = fmaf(w00, t[0], e0); e0 = fmaf(w01, t[1], e0); e0 = fmaf(w02, t[2], e0);
            e0 = fmaf(w10, m[0], e0); e0 = fmaf(w11, m[1], e0); e0 = fmaf(w12, m[2], e0);
            e0 = fmaf(w20, l[0], e0); e0 = fmaf(w21, l[1], e0); e0 = fmaf(w22, l[2], e0);
            e1 = fmaf(w00, t[1], e1); e1 = fmaf(w01, t[2], e1); e1 = fmaf(w02, t[3], e1);
            e1 = fmaf(w10, m[1], e1); e1 = fmaf(w11, m[2], e1); e1 = fmaf(w12, m[3], e1);
            e1 = fmaf(w20, l[1], e1); e1 = fmaf(w21, l[2], e1); e1 = fmaf(w22, l[3], e1);
            *(float2*)(out + (size_t)r * OW) = make_float2(e0, e1);
        }
    }
}

extern "C" void kernel_launch(void* const* d_in, const int* in_sizes, int n_in,
                              void* d_out, int out_size) {
    const float* x    = (const float*)d_in[0];
    const float* wgt  = (const float*)d_in[1];
    const float* bias = (const float*)d_in[2];
    float* out = (float*)d_out;

    dim3 block(TPB, 1, 1);
    dim3 grid((OW + TPB * 4 - 1) / (TPB * 4),   // 16
              (OH + RPT - 1) / RPT,             // 512
              1);
    Conv2D_35210141892837_kernel<<<grid, block>>>(x, wgt, bias, out);
}